// round 8
// baseline (speedup 1.0000x reference)
#include <cuda_runtime.h>
#include <math.h>

#define BB 32
#define CC 64
#define HH 128
#define WW 128
#define HW (HH*WW)          // 16384
#define HW4 (HW/4)          // 4096
#define C_R 38
#define C_IR 26
#define BN_EPS 1e-5f

#define GRP 8               // batches per L2-resident group (8*4.2MB = 33.5MB)
#define NG  (BB/GRP)        // 4 groups

// Scratch (device globals; no allocation allowed)
__device__ float4 g_part0[BB*HW];   // (rsum, rmax, isum, imax) channels 0..31
__device__ float4 g_part1[BB*HW];   // (rsum, rmax, isum, imax) channels 32..63
__device__ float  g_A1[BB*HW];
__device__ float  g_A2[BB*HW];
__device__ unsigned long long g_mask[BB];

// ---------------------------------------------------------------------------
// Kernel 1: per-batch top-k (k=38) channel mask from M[b,c].
// Rank rule matches jax.lax.top_k: larger value first, ties -> smaller index.
// ---------------------------------------------------------------------------
__global__ void topk_mask_kernel(const float* __restrict__ M) {
    int b = blockIdx.x;
    int c = threadIdx.x;
    __shared__ float m[CC];
    __shared__ unsigned wbal[2];
    m[c] = M[b * CC + c];
    __syncthreads();
    float mv = m[c];
    int rank = 0;
#pragma unroll
    for (int j = 0; j < CC; j++) {
        float mj = m[j];
        rank += (mj > mv) || (mj == mv && j < c);
    }
    unsigned bal = __ballot_sync(0xffffffffu, rank < C_R);
    if ((c & 31) == 0) wbal[c >> 5] = bal;
    __syncthreads();
    if (c == 0)
        g_mask[b] = (unsigned long long)wbal[0] |
                    ((unsigned long long)wbal[1] << 32);
}

// ---------------------------------------------------------------------------
// Kernel 2: partial channel reduction for ONE group of GRP batches.
// blockIdx.y selects channel half (32 channels). Plain cached loads so the
// x-chunk stays L2-resident for apply_kernel. Partial (sum, max) per half;
// merged in conv. Max floor 0 is exact: the reference maxes over mask*x,
// which always contains zeros from the opposite partition.
// ---------------------------------------------------------------------------
__global__ void stats_kernel(const float* __restrict__ x, int base_b) {
    int t = blockIdx.x * blockDim.x + threadIdx.x;   // 0 .. GRP*HW4-1
    int half = blockIdx.y;                            // 0 or 1
    int bl = t >> 12;
    int p  = t & (HW4 - 1);
    int b  = base_b + bl;
    unsigned m32 = (unsigned)(g_mask[b] >> (half << 5));
    const float4* xb = (const float4*)x
                     + ((size_t)b * CC + (half << 5)) * HW4 + p;

    float4 rs = make_float4(0.f,0.f,0.f,0.f), is = rs;
    float4 rm = rs, im = rs;

#pragma unroll 8
    for (int c = 0; c < 32; c++) {
        float4 v = __ldg(xb + c * HW4);
        float fr = (float)((m32 >> c) & 1u);
        float fi = 1.0f - fr;
        float vrx = v.x * fr, vry = v.y * fr, vrz = v.z * fr, vrw = v.w * fr;
        float vix = v.x * fi, viy = v.y * fi, viz = v.z * fi, viw = v.w * fi;
        rs.x += vrx; rs.y += vry; rs.z += vrz; rs.w += vrw;
        is.x += vix; is.y += viy; is.z += viz; is.w += viw;
        rm.x = fmaxf(rm.x, vrx); rm.y = fmaxf(rm.y, vry);
        rm.z = fmaxf(rm.z, vrz); rm.w = fmaxf(rm.w, vrw);
        im.x = fmaxf(im.x, vix); im.y = fmaxf(im.y, viy);
        im.z = fmaxf(im.z, viz); im.w = fmaxf(im.w, viw);
    }
    float4* dst = half ? g_part1 : g_part0;
    int pix = (b * HW) + (p << 2);
    dst[pix + 0] = make_float4(rs.x, rm.x, is.x, im.x);
    dst[pix + 1] = make_float4(rs.y, rm.y, is.y, im.y);
    dst[pix + 2] = make_float4(rs.z, rm.z, is.z, im.z);
    dst[pix + 3] = make_float4(rs.w, rm.w, is.w, im.w);
}

// ---------------------------------------------------------------------------
// Kernel 3: merge partials + 7x7 conv (pad 3) + BN + relu + sigmoid for one
// group. 16x16 tile, 22x22 halo; two float4 loads per halo pixel (L2-hit).
// ---------------------------------------------------------------------------
__global__ void conv_gate_kernel(const float* __restrict__ w,
                                 const float* __restrict__ gamma,
                                 const float* __restrict__ beta,
                                 const float* __restrict__ mean,
                                 const float* __restrict__ var,
                                 int base_b) {
    __shared__ float4 s[22][23];
    __shared__ float sw[98];
    __shared__ float sbn[2];

    int b  = base_b + blockIdx.z;
    int ty0 = blockIdx.y * 16, tx0 = blockIdx.x * 16;
    int tid = threadIdx.y * 16 + threadIdx.x;

    if (tid < 98) sw[tid] = w[tid];
    if (tid == 98) {
        float sc = rsqrtf(var[0] + BN_EPS) * gamma[0];
        sbn[0] = sc;
        sbn[1] = beta[0] - mean[0] * sc;
    }
    const float inv_r  = 1.0f / (float)C_R;
    const float inv_ir = 1.0f / (float)C_IR;
    int base = b * HW;
    const float4 zero4 = make_float4(0.f,0.f,0.f,0.f);
    for (int i = tid; i < 22 * 22; i += 256) {
        int ly = i / 22, lx = i - ly * 22;
        int gy = ty0 + ly - 3, gx = tx0 + lx - 3;
        bool ok = (gy >= 0) & (gy < HH) & (gx >= 0) & (gx < WW);
        float4 merged = zero4;
        if (ok) {
            int gi = base + gy * WW + gx;
            float4 a = g_part0[gi];
            float4 c2 = g_part1[gi];
            merged = make_float4((a.x + c2.x) * inv_r,  fmaxf(a.y, c2.y),
                                 (a.z + c2.z) * inv_ir, fmaxf(a.w, c2.w));
        }
        s[ly][lx] = merged;
    }
    __syncthreads();

    int ty = threadIdx.y, tx = threadIdx.x;
    float a1 = 0.f, a2 = 0.f;
#pragma unroll
    for (int ky = 0; ky < 7; ky++) {
#pragma unroll
        for (int kx = 0; kx < 7; kx++) {
            float w0 = sw[ky * 7 + kx];
            float w1 = sw[49 + ky * 7 + kx];
            float4 v = s[ty + ky][tx + kx];
            a1 += w0 * v.x + w1 * v.y;
            a2 += w0 * v.z + w1 * v.w;
        }
    }
    float sc = sbn[0], sh = sbn[1];
    a1 = fmaxf(a1 * sc + sh, 0.f);
    a2 = fmaxf(a2 * sc + sh, 0.f);
    a1 = 1.f / (1.f + expf(-a1));
    a2 = 1.f / (1.f + expf(-a2));

    int o = base + (ty0 + ty) * WW + (tx0 + tx);
    g_A1[o] = a1;
    g_A2[o] = a2;
}

// ---------------------------------------------------------------------------
// Kernel 4: out = x * (maskbit ? A1 : A2) for one group. x reads should hit
// L2 (chunk loaded by stats_kernel of the same group). __stcs on out keeps
// output lines evict-first so they don't displace the x-chunk.
// ---------------------------------------------------------------------------
__global__ void apply_kernel(const float* __restrict__ x,
                             float* __restrict__ out, int base_b) {
    int i = blockIdx.x * blockDim.x + threadIdx.x;   // 0 .. GRP*CC*HW4/2-1
    int local = i << 1;
    int g = base_b * CC * HW4 + local;
    int p  = local & (HW4 - 1);
    int bcl = local >> 12;
    int c  = bcl & 63;
    int b  = base_b + (bcl >> 6);
    bool rel = (g_mask[b] >> c) & 1ull;
    const float4* Ap = (const float4*)(rel ? g_A1 : g_A2) + b * HW4 + p;
    float4 a0 = __ldg(Ap);
    float4 a1 = __ldg(Ap + 1);
    float4 v0 = __ldg((const float4*)x + g);
    float4 v1 = __ldg((const float4*)x + g + 1);
    float4 o0, o1;
    o0.x = v0.x * a0.x; o0.y = v0.y * a0.y; o0.z = v0.z * a0.z; o0.w = v0.w * a0.w;
    o1.x = v1.x * a1.x; o1.y = v1.y * a1.y; o1.z = v1.z * a1.z; o1.w = v1.w * a1.w;
    __stcs((float4*)out + g,     o0);
    __stcs((float4*)out + g + 1, o1);
}

// ---------------------------------------------------------------------------
extern "C" void kernel_launch(void* const* d_in, const int* in_sizes, int n_in,
                              void* d_out, int out_size) {
    const float* x      = (const float*)d_in[0];
    const float* M      = (const float*)d_in[1];
    const float* conv_w = (const float*)d_in[2];
    const float* gamma  = (const float*)d_in[3];
    const float* beta   = (const float*)d_in[4];
    const float* mean   = (const float*)d_in[5];
    const float* var    = (const float*)d_in[6];
    float* out = (float*)d_out;

    topk_mask_kernel<<<BB, CC>>>(M);

    for (int gidx = 0; gidx < NG; gidx++) {
        int base_b = gidx * GRP;

        {   // stats: GRP*HW4 threads per channel-half
            dim3 grd((GRP * HW4) / 256, 2);
            stats_kernel<<<grd, 256>>>(x, base_b);
        }
        {   // conv gates for this group
            dim3 blk(16, 16);
            dim3 grd(WW / 16, HH / 16, GRP);
            conv_gate_kernel<<<grd, blk>>>(conv_w, gamma, beta, mean, var, base_b);
        }
        {   // apply for this group (x-chunk still L2-resident)
            int total = (GRP * CC * HW4) / 2;     // 1048576
            apply_kernel<<<total / 256, 256>>>(x, out, base_b);
        }
    }
}